// round 12
// baseline (speedup 1.0000x reference)
#include <cuda_runtime.h>
#include <cuda_fp16.h>
#include <math.h>
#include <stdint.h>

#define BATCH 2
#define SEQ   2048
#define DM    1024
#define NH    16
#define NKV   4
#define DK    64
#define QKVN  1536
#define ROWS  (BATCH*SEQ)
#define GROUPS (NH/NKV)
#define GK    1024

// ---------------- scratch (fp16 packed pairs in uint32) ----------------
__device__ uint32_t g_xhi[ROWS * GK / 2],  g_xlo[ROWS * GK / 2];
__device__ uint32_t g_wh [2560 * GK / 2];
__device__ uint32_t g_ahi[ROWS * DM / 2],  g_alo[ROWS * DM / 2];
__device__ uint32_t g_qh [BATCH * NH  * SEQ * DK / 2];   // Q single fp16 (scaled)
__device__ uint32_t g_kh [BATCH * NKV * SEQ * DK / 2];
__device__ uint32_t g_vh [BATCH * NKV * SEQ * DK / 2];

// ================= helpers =================
__device__ __forceinline__ uint32_t smem_to_u32(const void* p) {
    uint32_t a;
    asm("{ .reg .u64 t; cvta.to.shared.u64 t, %1; cvt.u32.u64 %0, t; }" : "=r"(a) : "l"(p));
    return a;
}
__device__ __forceinline__ float ex2(float x) {
    float r; asm("ex2.approx.f32 %0, %1;" : "=f"(r) : "f"(x)); return r;
}
__device__ __forceinline__ uint32_t pack_h2(float lo, float hi) {
    uint32_t r;
    asm("cvt.rn.f16x2.f32 %0, %1, %2;" : "=r"(r) : "f"(hi), "f"(lo));
    return r;
}
__device__ __forceinline__ void splitH2(float2 v, uint32_t& hi, uint32_t& lo) {
    __half h0 = __float2half_rn(v.x);
    __half h1 = __float2half_rn(v.y);
    float r0 = v.x - __half2float(h0);
    float r1 = v.y - __half2float(h1);
    hi = (uint32_t)__half_as_ushort(h0) | ((uint32_t)__half_as_ushort(h1) << 16);
    lo = pack_h2(r0, r1);
}
__device__ __forceinline__ void cp16(uint32_t saddr, const void* gaddr) {
    asm volatile("cp.async.cg.shared.global [%0], [%1], 16;" :: "r"(saddr), "l"(gaddr));
}
#define CP_COMMIT() asm volatile("cp.async.commit_group;")
#define CP_WAIT(N)  asm volatile("cp.async.wait_group %0;" :: "n"(N))

__device__ __forceinline__ void ldsm4(uint32_t* r, uint32_t addr) {
    asm volatile("ldmatrix.sync.aligned.m8n8.x4.shared.b16 {%0,%1,%2,%3}, [%4];"
        : "=r"(r[0]), "=r"(r[1]), "=r"(r[2]), "=r"(r[3]) : "r"(addr));
}
__device__ __forceinline__ void ldsm4t(uint32_t* r, uint32_t addr) {
    asm volatile("ldmatrix.sync.aligned.m8n8.x4.trans.shared.b16 {%0,%1,%2,%3}, [%4];"
        : "=r"(r[0]), "=r"(r[1]), "=r"(r[2]), "=r"(r[3]) : "r"(addr));
}
__device__ __forceinline__ void mma16816h(float* c, const uint32_t* a, uint32_t b0, uint32_t b1) {
    asm volatile("mma.sync.aligned.m16n8k16.row.col.f32.f16.f16.f32 "
        "{%0,%1,%2,%3}, {%4,%5,%6,%7}, {%8,%9}, {%0,%1,%2,%3};"
        : "+f"(c[0]), "+f"(c[1]), "+f"(c[2]), "+f"(c[3])
        : "r"(a[0]), "r"(a[1]), "r"(a[2]), "r"(a[3]), "r"(b0), "r"(b1));
}

// ================= split / pack kernels =================
__global__ void split_f16(const float* __restrict__ src, uint32_t* __restrict__ hi,
                          uint32_t* __restrict__ lo, int npairs) {
    int i = blockIdx.x * blockDim.x + threadIdx.x;
    if (i < npairs) {
        float2 v = ((const float2*)src)[i];
        uint32_t h, l;
        splitH2(v, h, l);
        hi[i] = h;
        lo[i] = l;
    }
}
__global__ void pack_f16(const float* __restrict__ src, uint32_t* __restrict__ dst, int npairs) {
    int i = blockIdx.x * blockDim.x + threadIdx.x;
    if (i < npairs) {
        float2 v = ((const float2*)src)[i];
        dst[i] = pack_h2(v.x, v.y);
    }
}

// ================= fp16x2 GEMM, CTA tile 128x256, 512 threads, 3-stage =================
// warp grid 4m x 4n; warp tile 32m x 64n. Stage = Ahi(16K)|Alo(16K)|B(32K) = 64KB.
template<bool FUSE_QKV>
__global__ __launch_bounds__(512, 1) void gemm_f16x2(
        const __half* __restrict__ Ahi, const __half* __restrict__ Alo,
        const __half* __restrict__ Bh, float* __restrict__ C, int N,
        const float* __restrict__ qw, const float* __restrict__ kw) {
    extern __shared__ char smc[];
    const uint32_t sb = smem_to_u32(smc);
    const int tid = threadIdx.x;
    const int wid = tid >> 5, lane = tid & 31;
    const int wm = wid >> 2, wn = wid & 3;
    const int row0 = blockIdx.y * 128, col0 = blockIdx.x * 256;

    auto stA_hi = [&](int s) { return sb + s * 65536u; };
    auto stA_lo = [&](int s) { return sb + s * 65536u + 16384u; };
    auto stB    = [&](int s) { return sb + s * 65536u + 32768u; };

    auto load_stage = [&](int s, int kt) {
        const int k0 = kt * 64;
        #pragma unroll
        for (int i = 0; i < 2; i++) {          // A: 128 rows x 8 chunks, 2 planes
            int idx = tid + i * 512;
            int r = idx >> 3, c = idx & 7;
            uint32_t soff = (uint32_t)(r * 128 + ((c ^ (r & 7)) << 4));
            size_t gbyte = ((size_t)(row0 + r) * GK + k0) * 2 + c * 16;
            cp16(stA_hi(s) + soff, (const char*)Ahi + gbyte);
            cp16(stA_lo(s) + soff, (const char*)Alo + gbyte);
        }
        #pragma unroll
        for (int i = 0; i < 4; i++) {          // B: 256 rows x 8 chunks
            int idx = tid + i * 512;
            int r = idx >> 3, c = idx & 7;
            uint32_t soff = (uint32_t)(r * 128 + ((c ^ (r & 7)) << 4));
            size_t gbyte = ((size_t)(col0 + r) * GK + k0) * 2 + c * 16;
            cp16(stB(s) + soff, (const char*)Bh + gbyte);
        }
    };

    float acc[2][8][4];
    #pragma unroll
    for (int i = 0; i < 2; i++)
        #pragma unroll
        for (int j = 0; j < 8; j++)
            #pragma unroll
            for (int e = 0; e < 4; e++) acc[i][j][e] = 0.0f;

    load_stage(0, 0); CP_COMMIT();
    load_stage(1, 1); CP_COMMIT();

    const int lrow = lane & 15, khalf = lane >> 4;

    for (int kt = 0; kt < 16; kt++) {
        if (kt < 15) CP_WAIT(1); else CP_WAIT(0);
        __syncthreads();
        if (kt + 2 < 16) { load_stage((kt + 2) % 3, kt + 2); CP_COMMIT(); }

        const int s = kt % 3;
        const uint32_t aHi = stA_hi(s), aLo = stA_lo(s), bH = stB(s);

        #pragma unroll
        for (int ks = 0; ks < 4; ks++) {
            const int c = ks * 2 + khalf;
            uint32_t ah[2][4], al[2][4];
            #pragma unroll
            for (int ma = 0; ma < 2; ma++) {
                int r = wm * 32 + ma * 16 + lrow;
                uint32_t off = (uint32_t)(r * 128 + ((c ^ (r & 7)) << 4));
                ldsm4(ah[ma], aHi + off);
                ldsm4(al[ma], aLo + off);
            }
            #pragma unroll
            for (int nb = 0; nb < 4; nb++) {
                int r = wn * 64 + nb * 16 + lrow;
                uint32_t off = (uint32_t)(r * 128 + ((c ^ (r & 7)) << 4));
                uint32_t bh[4];
                ldsm4(bh, bH + off);
                #pragma unroll
                for (int ma = 0; ma < 2; ma++) {
                    mma16816h(acc[ma][nb * 2],     ah[ma], bh[0], bh[2]);
                    mma16816h(acc[ma][nb * 2],     al[ma], bh[0], bh[2]);
                    mma16816h(acc[ma][nb * 2 + 1], ah[ma], bh[1], bh[3]);
                    mma16816h(acc[ma][nb * 2 + 1], al[ma], bh[1], bh[3]);
                }
            }
        }
    }

    const int crow = lane >> 2, ccl = lane & 3;

    if (!FUSE_QKV) {
        const int ccol = ccl * 2;
        #pragma unroll
        for (int ma = 0; ma < 2; ma++) {
            #pragma unroll
            for (int na = 0; na < 8; na++) {
                int r = row0 + wm * 32 + ma * 16 + crow;
                int cc = col0 + wn * 64 + na * 8 + ccol;
                *(float2*)&C[(size_t)r * N + cc]       = make_float2(acc[ma][na][0], acc[ma][na][1]);
                *(float2*)&C[(size_t)(r + 8) * N + cc] = make_float2(acc[ma][na][2], acc[ma][na][3]);
            }
        }
        return;
    }

    // ---------- fused RMSNorm + RoPE + fp16 pack epilogue ----------
    const int slot = (col0 + wn * 64) >> 6;   // one full head per warp

    if (slot >= NH + NKV) {            // V
        const int hv = slot - NH - NKV;
        #pragma unroll
        for (int ma = 0; ma < 2; ma++)
            #pragma unroll
            for (int rr = 0; rr < 2; rr++) {
                const int row = row0 + wm * 32 + ma * 16 + rr * 8 + crow;
                const int b = row >> 11, t = row & (SEQ - 1);
                const size_t base = (((size_t)b * NKV + hv) * SEQ + t) * 32;
                #pragma unroll
                for (int na = 0; na < 8; na++) {
                    const int i = na * 4 + ccl;
                    g_vh[base + i] = pack_h2(acc[ma][na][rr * 2], acc[ma][na][rr * 2 + 1]);
                }
            }
        return;
    }

    const bool isQ = (slot < NH);
    const float* w = isQ ? qw : kw;
    float w0[8], w1[8], invf[8];
    #pragma unroll
    for (int na = 0; na < 8; na++) {
        const int i = na * 4 + ccl;
        w0[na] = w[2 * i];
        w1[na] = w[2 * i + 1];
        invf[na] = __powf(10000.0f, -(float)(2 * i) / (float)DK);
    }
    const float qs = 0.125f * 1.4426950408889634f;

    #pragma unroll
    for (int ma = 0; ma < 2; ma++)
        #pragma unroll
        for (int rr = 0; rr < 2; rr++) {
            const int row = row0 + wm * 32 + ma * 16 + rr * 8 + crow;
            const int b = row >> 11, t = row & (SEQ - 1);

            float ss = 0.0f;
            #pragma unroll
            for (int na = 0; na < 8; na++) {
                float v0 = acc[ma][na][rr * 2], v1 = acc[ma][na][rr * 2 + 1];
                ss += v0 * v0 + v1 * v1;
            }
            ss += __shfl_xor_sync(0xffffffffu, ss, 1);
            ss += __shfl_xor_sync(0xffffffffu, ss, 2);
            const float rnorm = rsqrtf(ss * (1.0f / DK) + 1.1920929e-07f);

            const size_t base = isQ
                ? (((size_t)b * NH + slot) * SEQ + t) * 32
                : (((size_t)b * NKV + (slot - NH)) * SEQ + t) * 32;

            #pragma unroll
            for (int na = 0; na < 8; na++) {
                const int i = na * 4 + ccl;
                float y0 = acc[ma][na][rr * 2]     * rnorm * w0[na];
                float y1 = acc[ma][na][rr * 2 + 1] * rnorm * w1[na];
                float sv, cv;
                sincosf((float)t * invf[na], &sv, &cv);
                float o0 = y0 * cv - y1 * sv;
                float o1 = y0 * sv + y1 * cv;
                if (isQ) {
                    g_qh[base + i] = pack_h2(o0 * qs, o1 * qs);
                } else {
                    g_kh[base + i] = pack_h2(o0, o1);
                }
            }
        }
}

// ================= tensor-core causal flash attention, 512 threads =================
// warp grid 8(q) x 2(kv): warp = 16 q-rows x 64 kv-cols. Q/K/V single fp16.
// Fixed-base exp2 softmax; kv-half partials combined via smem.
__global__ __launch_bounds__(512, 1) void attn_mma() {
    extern __shared__ char sma[];
    const uint32_t sb = smem_to_u32(sma);
    const int tid = threadIdx.x;
    const int wid = tid >> 5, lane = tid & 31;
    const int wq = wid >> 1, wk = wid & 1;
    const int qb = (int)gridDim.x - 1 - (int)blockIdx.x;
    const int h  = blockIdx.y, b = blockIdx.z;
    const int kvh = h / GROUPS;

    auto KH = [&](int s) { return sb + s * 32768u; };
    auto VH = [&](int s) { return sb + s * 32768u + 16384u; };

    const char* qhB = (const char*)g_qh + (((size_t)b * NH + h) * SEQ + (size_t)qb * 128) * 128;
    const char* khB = (const char*)g_kh + ((size_t)b * NKV + kvh) * SEQ * 128;
    const char* vhB = (const char*)g_vh + ((size_t)b * NKV + kvh) * SEQ * 128;

    // ---- stage Q (16KB single plane), load fragments ----
    {
        #pragma unroll
        for (int i = 0; i < 2; i++) {
            int idx = tid + i * 512;
            int r = idx >> 3, c = idx & 7;
            uint32_t soff = (uint32_t)(r * 128 + ((c ^ (r & 7)) << 4));
            cp16(sb + soff, qhB + (size_t)r * 128 + c * 16);
        }
        CP_COMMIT(); CP_WAIT(0);
        __syncthreads();
    }
    const int lrow = lane & 15, khalf = lane >> 4;
    uint32_t qh[4][4];
    {
        const int r = wq * 16 + lrow;
        #pragma unroll
        for (int ks = 0; ks < 4; ks++) {
            const int c = ks * 2 + khalf;
            uint32_t off = (uint32_t)(r * 128 + ((c ^ (r & 7)) << 4));
            ldsm4(qh[ks], sb + off);
        }
    }
    __syncthreads();

    auto load_kv = [&](int s, int kb) {
        #pragma unroll
        for (int i = 0; i < 2; i++) {
            int idx = tid + i * 512;
            int r = idx >> 3, c = idx & 7;
            uint32_t soff = (uint32_t)(r * 128 + ((c ^ (r & 7)) << 4));
            size_t gb = ((size_t)kb * 128 + r) * 128 + c * 16;
            cp16(KH(s) + soff, khB + gb);
            cp16(VH(s) + soff, vhB + gb);
        }
    };

    const int nkb = qb + 1;
    float oa[8][4];
    #pragma unroll
    for (int j = 0; j < 8; j++)
        #pragma unroll
        for (int e = 0; e < 4; e++) oa[j][e] = 0.0f;
    float l0 = 0.0f, l1 = 0.0f;

    const int gr0 = qb * 128 + wq * 16 + (lane >> 2);
    const int gr1 = gr0 + 8;
    const int vrow_base = ((lane >> 3) & 1) * 8 + (lane & 7);
    const int vkh = lane >> 4;

    load_kv(0, 0);
    CP_COMMIT();

    for (int kb = 0; kb < nkb; kb++) {
        CP_WAIT(0);
        __syncthreads();
        if (kb + 1 < nkb) { load_kv((kb + 1) & 1, kb + 1); CP_COMMIT(); }

        const int s = kb & 1;
        const uint32_t kH = KH(s), vH = VH(s);

        // ---- S = Q K^T (single fp16 chain) ----
        float sc[8][4];
        #pragma unroll
        for (int j = 0; j < 8; j++)
            #pragma unroll
            for (int e = 0; e < 4; e++) sc[j][e] = 0.0f;

        #pragma unroll
        for (int ks = 0; ks < 4; ks++) {
            const int c = ks * 2 + khalf;
            #pragma unroll
            for (int nb = 0; nb < 4; nb++) {
                int r = wk * 64 + nb * 16 + lrow;
                uint32_t off = (uint32_t)(r * 128 + ((c ^ (r & 7)) << 4));
                uint32_t kh[4];
                ldsm4(kh, kH + off);
                mma16816h(sc[2 * nb],     qh[ks], kh[0], kh[2]);
                mma16816h(sc[2 * nb + 1], qh[ks], kh[1], kh[3]);
            }
        }

        // ---- causal mask (diagonal tile only) ----
        if (kb == qb) {
            #pragma unroll
            for (int j = 0; j < 8; j++) {
                const int c0 = kb * 128 + wk * 64 + 8 * j + (lane & 3) * 2;
                const int c1 = c0 + 1;
                if (c0 > gr0) sc[j][0] = -INFINITY;
                if (c1 > gr0) sc[j][1] = -INFINITY;
                if (c0 > gr1) sc[j][2] = -INFINITY;
                if (c1 > gr1) sc[j][3] = -INFINITY;
            }
        }

        // ---- fixed-base softmax ----
        #pragma unroll
        for (int j = 0; j < 8; j++) {
            sc[j][0] = ex2(sc[j][0]);
            sc[j][1] = ex2(sc[j][1]);
            sc[j][2] = ex2(sc[j][2]);
            sc[j][3] = ex2(sc[j][3]);
            l0 += sc[j][0] + sc[j][1];
            l1 += sc[j][2] + sc[j][3];
        }

        // ---- P fragments as fp16 ----
        uint32_t pa[4][4];
        #pragma unroll
        for (int kk = 0; kk < 4; kk++) {
            pa[kk][0] = pack_h2(sc[2 * kk][0],     sc[2 * kk][1]);
            pa[kk][1] = pack_h2(sc[2 * kk][2],     sc[2 * kk][3]);
            pa[kk][2] = pack_h2(sc[2 * kk + 1][0], sc[2 * kk + 1][1]);
            pa[kk][3] = pack_h2(sc[2 * kk + 1][2], sc[2 * kk + 1][3]);
        }

        // ---- O += P V (fp16 single chain) ----
        #pragma unroll
        for (int kk = 0; kk < 4; kk++) {
            const int vr = wk * 64 + kk * 16 + vrow_base;
            #pragma unroll
            for (int ng = 0; ng < 4; ng++) {
                const int vc = ng * 2 + vkh;
                uint32_t off = (uint32_t)(vr * 128 + ((vc ^ (vr & 7)) << 4));
                uint32_t vh[4];
                ldsm4t(vh, vH + off);
                mma16816h(oa[2 * ng],     pa[kk], vh[0], vh[1]);
                mma16816h(oa[2 * ng + 1], pa[kk], vh[2], vh[3]);
            }
        }
    }

    // ---- quad-reduce l, combine kv-half partials via smem ----
    l0 += __shfl_xor_sync(0xffffffffu, l0, 1);
    l0 += __shfl_xor_sync(0xffffffffu, l0, 2);
    l1 += __shfl_xor_sync(0xffffffffu, l1, 1);
    l1 += __shfl_xor_sync(0xffffffffu, l1, 2);

    float* xch = (float*)sma;                 // 8 wq x 32 lanes x 34 floats = 34.8KB
    __syncthreads();
    if (wk == 1) {
        float* dst = xch + (wq * 32 + lane) * 34;
        #pragma unroll
        for (int j = 0; j < 8; j++) {
            dst[j * 4 + 0] = oa[j][0]; dst[j * 4 + 1] = oa[j][1];
            dst[j * 4 + 2] = oa[j][2]; dst[j * 4 + 3] = oa[j][3];
        }
        dst[32] = l0; dst[33] = l1;
    }
    __syncthreads();
    if (wk == 1) return;

    {
        const float* src = xch + (wq * 32 + lane) * 34;
        #pragma unroll
        for (int j = 0; j < 8; j++) {
            oa[j][0] += src[j * 4 + 0]; oa[j][1] += src[j * 4 + 1];
            oa[j][2] += src[j * 4 + 2]; oa[j][3] += src[j * 4 + 3];
        }
        l0 += src[32]; l1 += src[33];
    }

    const float inv0 = 1.0f / l0, inv1 = 1.0f / l1;
    const int t0 = qb * 128 + wq * 16 + (lane >> 2);
    const size_t row0 = (size_t)b * SEQ + t0;
    const size_t row1 = row0 + 8;
    #pragma unroll
    for (int j = 0; j < 8; j++) {
        const int cidx = h * 32 + j * 4 + (lane & 3);
        uint32_t hi, lo;
        splitH2(make_float2(oa[j][0] * inv0, oa[j][1] * inv0), hi, lo);
        g_ahi[row0 * 512 + cidx] = hi;
        g_alo[row0 * 512 + cidx] = lo;
        splitH2(make_float2(oa[j][2] * inv1, oa[j][3] * inv1), hi, lo);
        g_ahi[row1 * 512 + cidx] = hi;
        g_alo[row1 * 512 + cidx] = lo;
    }
}

// ================= launch =================
extern "C" void kernel_launch(void* const* d_in, const int* in_sizes, int n_in,
                              void* d_out, int out_size) {
    const float* x    = (const float*)d_in[0];
    const float* qkvo = (const float*)d_in[1];
    const float* qw   = (const float*)d_in[2];
    const float* kw   = (const float*)d_in[3];
    float* out = (float*)d_out;

    void *p_xhi, *p_xlo, *p_wh, *p_ahi, *p_alo;
    cudaGetSymbolAddress(&p_xhi, g_xhi); cudaGetSymbolAddress(&p_xlo, g_xlo);
    cudaGetSymbolAddress(&p_wh, g_wh);
    cudaGetSymbolAddress(&p_ahi, g_ahi); cudaGetSymbolAddress(&p_alo, g_alo);

    const int GEMM_SMEM = 3 * 65536;   // 192 KB
    const int ATTN_SMEM = 2 * 32768;   // 64 KB
    cudaFuncSetAttribute(gemm_f16x2<true>,  cudaFuncAttributeMaxDynamicSharedMemorySize, GEMM_SMEM);
    cudaFuncSetAttribute(gemm_f16x2<false>, cudaFuncAttributeMaxDynamicSharedMemorySize, GEMM_SMEM);
    cudaFuncSetAttribute(attn_mma, cudaFuncAttributeMaxDynamicSharedMemorySize, ATTN_SMEM);

    // 0) split x (hi/lo) and pack weights (single fp16)
    {
        int np = ROWS * GK / 2;
        split_f16<<<np / 256, 256>>>(x, (uint32_t*)p_xhi, (uint32_t*)p_xlo, np);
        int nw = 2560 * GK / 2;
        pack_f16<<<nw / 256, 256>>>(qkvo, (uint32_t*)p_wh, nw);
    }

    // 1) QKV projection + fused RMSNorm/RoPE -> Q/K/V fp16 planes
    gemm_f16x2<true><<<dim3(QKVN / 256, ROWS / 128), 512, GEMM_SMEM>>>(
        (const __half*)p_xhi, (const __half*)p_xlo,
        (const __half*)p_wh, nullptr, QKVN, qw, kw);

    // 2) tensor-core causal flash attention -> g_ahi/g_alo
    attn_mma<<<dim3(SEQ / 128, NH, BATCH), 512, ATTN_SMEM>>>();

    // 3) O projection
    gemm_f16x2<false><<<dim3(DM / 256, ROWS / 128), 512, GEMM_SMEM>>>(
        (const __half*)p_ahi, (const __half*)p_alo,
        (const __half*)p_wh + (size_t)QKVN * GK, out, DM, nullptr, nullptr);
}

// round 13
// speedup vs baseline: 1.1585x; 1.1585x over previous
#include <cuda_runtime.h>
#include <cuda_fp16.h>
#include <math.h>
#include <stdint.h>

#define BATCH 2
#define SEQ   2048
#define DM    1024
#define NH    16
#define NKV   4
#define DK    64
#define QKVN  1536
#define ROWS  (BATCH*SEQ)
#define GROUPS (NH/NKV)
#define GK    1024

// ---------------- scratch: pre-swizzled 16KB panels (128 rows x 64 fp16 cols) ----------------
// panel u32 layout: idx = panel*4096 + r*32 + ((chunk ^ (r&7))<<2) + byte4,
// identical bytes to the old swizzled smem tiles.
__device__ __align__(128) uint32_t g_xhi[ROWS * GK / 2],  g_xlo[ROWS * GK / 2];
__device__ __align__(128) uint32_t g_wh [2560 * GK / 2];
__device__ __align__(128) uint32_t g_ahi[ROWS * DM / 2],  g_alo[ROWS * DM / 2];
__device__ __align__(128) uint32_t g_qh [BATCH * NH  * SEQ * DK / 2];
__device__ __align__(128) uint32_t g_kh [BATCH * NKV * SEQ * DK / 2];
__device__ __align__(128) uint32_t g_vh [BATCH * NKV * SEQ * DK / 2];

// ================= helpers =================
__device__ __forceinline__ uint32_t smem_to_u32(const void* p) {
    uint32_t a;
    asm("{ .reg .u64 t; cvta.to.shared.u64 t, %1; cvt.u32.u64 %0, t; }" : "=r"(a) : "l"(p));
    return a;
}
__device__ __forceinline__ float ex2(float x) {
    float r; asm("ex2.approx.f32 %0, %1;" : "=f"(r) : "f"(x)); return r;
}
__device__ __forceinline__ uint32_t pack_h2(float lo, float hi) {
    uint32_t r;
    asm("cvt.rn.f16x2.f32 %0, %1, %2;" : "=r"(r) : "f"(hi), "f"(lo));
    return r;
}
__device__ __forceinline__ void splitH2(float2 v, uint32_t& hi, uint32_t& lo) {
    __half h0 = __float2half_rn(v.x);
    __half h1 = __float2half_rn(v.y);
    float r0 = v.x - __half2float(h0);
    float r1 = v.y - __half2float(h1);
    hi = (uint32_t)__half_as_ushort(h0) | ((uint32_t)__half_as_ushort(h1) << 16);
    lo = pack_h2(r0, r1);
}
// u32 index inside panel array: cp = column-pair within 64-col panel (0..31)
__device__ __forceinline__ uint32_t panel_u32(uint32_t panel, int r, int cp) {
    int cl = cp >> 2;
    return panel * 4096u + (uint32_t)(r * 32 + ((cl ^ (r & 7)) << 2) + (cp & 3));
}

__device__ __forceinline__ void bulk_cp(uint32_t dst, const void* src, uint32_t bytes, uint32_t mbar) {
    asm volatile("cp.async.bulk.shared::cta.global.mbarrier::complete_tx::bytes [%0], [%1], %2, [%3];"
        :: "r"(dst), "l"(src), "r"(bytes), "r"(mbar) : "memory");
}
#define MBARRIER_INIT(mbar, count) \
    asm volatile("mbarrier.init.shared.b64 [%0], %1;" \
        :: "r"((uint32_t)(mbar)), "r"((uint32_t)(count)) : "memory")
#define MBARRIER_EXPECT_TX(mbar, bytes) \
    asm volatile("mbarrier.arrive.expect_tx.shared.b64 _, [%0], %1;" \
        :: "r"((uint32_t)(mbar)), "r"((uint32_t)(bytes)) : "memory")
#define MBARRIER_WAIT(mbar_addr, parity) do { \
    uint32_t _mbar = (uint32_t)(mbar_addr); \
    uint32_t _par = (uint32_t)(parity); \
    uint32_t _done; \
    asm volatile("{\n\t.reg .pred p;\n\t" \
        "mbarrier.try_wait.parity.acquire.cta.shared::cta.b64 p, [%1], %2;\n\t" \
        "selp.b32 %0, 1, 0, p;\n\t}" : "=r"(_done) : "r"(_mbar), "r"(_par) : "memory"); \
    if (!_done) { \
        asm volatile("{\n\t.reg .pred P1;\n\t" \
            "WAIT_LOOP_%=:\n\t" \
            "mbarrier.try_wait.parity.acquire.cta.shared::cta.b64 P1, [%0], %1, 0x989680;\n\t" \
            "@P1 bra.uni WAIT_DONE_%=;\n\t" \
            "bra.uni WAIT_LOOP_%=;\n\t" \
            "WAIT_DONE_%=:\n\t}" :: "r"(_mbar), "r"(_par) : "memory"); \
    } \
} while(0)

__device__ __forceinline__ void ldsm4(uint32_t* r, uint32_t addr) {
    asm volatile("ldmatrix.sync.aligned.m8n8.x4.shared.b16 {%0,%1,%2,%3}, [%4];"
        : "=r"(r[0]), "=r"(r[1]), "=r"(r[2]), "=r"(r[3]) : "r"(addr));
}
__device__ __forceinline__ void ldsm4t(uint32_t* r, uint32_t addr) {
    asm volatile("ldmatrix.sync.aligned.m8n8.x4.trans.shared.b16 {%0,%1,%2,%3}, [%4];"
        : "=r"(r[0]), "=r"(r[1]), "=r"(r[2]), "=r"(r[3]) : "r"(addr));
}
__device__ __forceinline__ void mma16816h(float* c, const uint32_t* a, uint32_t b0, uint32_t b1) {
    asm volatile("mma.sync.aligned.m16n8k16.row.col.f32.f16.f16.f32 "
        "{%0,%1,%2,%3}, {%4,%5,%6,%7}, {%8,%9}, {%0,%1,%2,%3};"
        : "+f"(c[0]), "+f"(c[1]), "+f"(c[2]), "+f"(c[3])
        : "r"(a[0]), "r"(a[1]), "r"(a[2]), "r"(a[3]), "r"(b0), "r"(b1));
}

// ================= split / pack into panel layout =================
// input row-major [rows][512 pairs]; panel = (row>>7)*16 + (cp>>5)
__global__ void split_f16_panel(const float* __restrict__ src, uint32_t* __restrict__ hi,
                                uint32_t* __restrict__ lo, int npairs) {
    int i = blockIdx.x * blockDim.x + threadIdx.x;
    if (i < npairs) {
        float2 v = ((const float2*)src)[i];
        uint32_t h, l;
        splitH2(v, h, l);
        int row = i >> 9, cp = i & 511;
        uint32_t idx = panel_u32((uint32_t)((row >> 7) * 16 + (cp >> 5)), row & 127, cp & 31);
        hi[idx] = h;
        lo[idx] = l;
    }
}
__global__ void pack_f16_panel(const float* __restrict__ src, uint32_t* __restrict__ dst, int npairs) {
    int i = blockIdx.x * blockDim.x + threadIdx.x;
    if (i < npairs) {
        float2 v = ((const float2*)src)[i];
        int row = i >> 9, cp = i & 511;
        uint32_t idx = panel_u32((uint32_t)((row >> 7) * 16 + (cp >> 5)), row & 127, cp & 31);
        dst[i - i + idx] = pack_h2(v.x, v.y);
    }
}

// ================= fp16x2 GEMM, 128x128 tile, 512 threads, 4-stage bulk pipeline =================
// warp grid 8m x 2n; warp tile 16m x 64n. Stage = Ahi|Alo|B (48KB); mbars at +192KB.
template<bool FUSE_QKV>
__global__ __launch_bounds__(512, 1) void gemm_f16x2(
        const uint32_t* __restrict__ Ahi, const uint32_t* __restrict__ Alo,
        const uint32_t* __restrict__ Bh, float* __restrict__ C, int N,
        const float* __restrict__ qw, const float* __restrict__ kw) {
    extern __shared__ char smc[];
    const uint32_t sb = smem_to_u32(smc);
    const uint32_t MB = sb + 196608u;
    const int tid = threadIdx.x;
    const int wid = tid >> 5, lane = tid & 31;
    const int wm = wid >> 1, wn = wid & 1;
    const int mt = blockIdx.y, nt = blockIdx.x;

    if (tid == 0) {
        #pragma unroll
        for (int s = 0; s < 4; s++) MBARRIER_INIT(MB + s * 8, 1);
    }
    __syncthreads();

    auto issue = [&](int s, int kt) {
        MBARRIER_EXPECT_TX(MB + s * 8, 49152);
        bulk_cp(sb + s * 49152u,          Ahi + (size_t)(mt * 16 + kt) * 4096, 16384, MB + s * 8);
        bulk_cp(sb + s * 49152u + 16384u, Alo + (size_t)(mt * 16 + kt) * 4096, 16384, MB + s * 8);
        bulk_cp(sb + s * 49152u + 32768u, Bh  + (size_t)(nt * 16 + kt) * 4096, 16384, MB + s * 8);
    };
    if (tid == 0) { issue(0, 0); issue(1, 1); issue(2, 2); issue(3, 3); }

    float acc[8][4];
    #pragma unroll
    for (int j = 0; j < 8; j++)
        #pragma unroll
        for (int e = 0; e < 4; e++) acc[j][e] = 0.0f;

    const int lrow = lane & 15, khalf = lane >> 4;

    for (int kt = 0; kt < 16; kt++) {
        MBARRIER_WAIT(MB + (kt & 3) * 8, (kt >> 2) & 1);
        const uint32_t base = sb + (uint32_t)(kt & 3) * 49152u;
        const uint32_t aHi = base, aLo = base + 16384u, bH = base + 32768u;

        #pragma unroll
        for (int ks = 0; ks < 4; ks++) {
            const int c = ks * 2 + khalf;
            uint32_t ah[4], al[4];
            {
                int r = wm * 16 + lrow;
                uint32_t off = (uint32_t)(r * 128 + ((c ^ (r & 7)) << 4));
                ldsm4(ah, aHi + off);
                ldsm4(al, aLo + off);
            }
            #pragma unroll
            for (int nb = 0; nb < 4; nb++) {
                int r = wn * 64 + nb * 16 + lrow;
                uint32_t off = (uint32_t)(r * 128 + ((c ^ (r & 7)) << 4));
                uint32_t bh[4];
                ldsm4(bh, bH + off);
                mma16816h(acc[nb * 2],     ah, bh[0], bh[2]);
                mma16816h(acc[nb * 2],     al, bh[0], bh[2]);
                mma16816h(acc[nb * 2 + 1], ah, bh[1], bh[3]);
                mma16816h(acc[nb * 2 + 1], al, bh[1], bh[3]);
            }
        }
        __syncthreads();
        if (tid == 0 && kt + 4 < 16) issue(kt & 3, kt + 4);
    }

    const int crow = lane >> 2, ccl = lane & 3;

    if (!FUSE_QKV) {
        const int ccol = ccl * 2;
        #pragma unroll
        for (int na = 0; na < 8; na++) {
            int r = mt * 128 + wm * 16 + crow;
            int cc = nt * 128 + wn * 64 + na * 8 + ccol;
            *(float2*)&C[(size_t)r * N + cc]       = make_float2(acc[na][0], acc[na][1]);
            *(float2*)&C[(size_t)(r + 8) * N + cc] = make_float2(acc[na][2], acc[na][3]);
        }
        return;
    }

    // ---------- fused RMSNorm + RoPE + fp16 panel epilogue ----------
    const int slot = nt * 2 + wn;      // one full head per warp

    if (slot >= NH + NKV) {            // V panels
        const int hv = slot - NH - NKV;
        #pragma unroll
        for (int rr = 0; rr < 2; rr++) {
            const int row = mt * 128 + wm * 16 + rr * 8 + crow;
            const int b = row >> 11, t = row & (SEQ - 1);
            const uint32_t pan = (uint32_t)((b * NKV + hv) * 16 + (t >> 7));
            const int r = t & 127;
            #pragma unroll
            for (int na = 0; na < 8; na++)
                g_vh[panel_u32(pan, r, na * 4 + ccl)] = pack_h2(acc[na][rr * 2], acc[na][rr * 2 + 1]);
        }
        return;
    }

    const bool isQ = (slot < NH);
    const float* w = isQ ? qw : kw;
    float w0[8], w1[8], invf[8];
    #pragma unroll
    for (int na = 0; na < 8; na++) {
        const int i = na * 4 + ccl;
        w0[na] = w[2 * i];
        w1[na] = w[2 * i + 1];
        invf[na] = __powf(10000.0f, -(float)(2 * i) / (float)DK);
    }
    const float qs = 0.125f * 1.4426950408889634f;

    #pragma unroll
    for (int rr = 0; rr < 2; rr++) {
        const int row = mt * 128 + wm * 16 + rr * 8 + crow;
        const int b = row >> 11, t = row & (SEQ - 1);

        float ss = 0.0f;
        #pragma unroll
        for (int na = 0; na < 8; na++) {
            float v0 = acc[na][rr * 2], v1 = acc[na][rr * 2 + 1];
            ss += v0 * v0 + v1 * v1;
        }
        ss += __shfl_xor_sync(0xffffffffu, ss, 1);
        ss += __shfl_xor_sync(0xffffffffu, ss, 2);
        const float rnorm = rsqrtf(ss * (1.0f / DK) + 1.1920929e-07f);

        const uint32_t pan = isQ
            ? (uint32_t)((b * NH + slot) * 16 + (t >> 7))
            : (uint32_t)((b * NKV + (slot - NH)) * 16 + (t >> 7));
        const int r = t & 127;

        #pragma unroll
        for (int na = 0; na < 8; na++) {
            float y0 = acc[na][rr * 2]     * rnorm * w0[na];
            float y1 = acc[na][rr * 2 + 1] * rnorm * w1[na];
            float sv, cv;
            sincosf((float)t * invf[na], &sv, &cv);
            float o0 = y0 * cv - y1 * sv;
            float o1 = y0 * sv + y1 * cv;
            if (isQ) g_qh[panel_u32(pan, r, na * 4 + ccl)] = pack_h2(o0 * qs, o1 * qs);
            else     g_kh[panel_u32(pan, r, na * 4 + ccl)] = pack_h2(o0, o1);
        }
    }
}

// ================= tensor-core causal flash attention, 256 threads, bulk loads =================
// warp grid 4(q) x 2(kv): warp = 32 q-rows x 64 kv-cols. Q/K/V single fp16.
// smem: KV stage0 @0 (K|V 16KB each), stage1 @32768, Q @65536, mbars @81920.
__global__ __launch_bounds__(256, 1) void attn_mma() {
    extern __shared__ char sma[];
    const uint32_t sb = smem_to_u32(sma);
    const uint32_t MB = sb + 81920u;
    const int tid = threadIdx.x;
    const int wid = tid >> 5, lane = tid & 31;
    const int wq = wid >> 1, wk = wid & 1;
    const int qb = (int)gridDim.x - 1 - (int)blockIdx.x;
    const int h  = blockIdx.y, b = blockIdx.z;
    const int kvh = h / GROUPS;
    const int nkb = qb + 1;

    if (tid == 0) {
        MBARRIER_INIT(MB + 0, 1);
        MBARRIER_INIT(MB + 8, 1);
        MBARRIER_INIT(MB + 16, 1);
    }
    __syncthreads();

    const uint32_t qpan  = (uint32_t)((b * NH + h) * 16 + qb);
    const uint32_t kvpan = (uint32_t)((b * NKV + kvh) * 16);

    auto issue = [&](int s, int kb) {
        MBARRIER_EXPECT_TX(MB + s * 8, 32768);
        bulk_cp(sb + s * 32768u,          g_kh + (size_t)(kvpan + kb) * 4096, 16384, MB + s * 8);
        bulk_cp(sb + s * 32768u + 16384u, g_vh + (size_t)(kvpan + kb) * 4096, 16384, MB + s * 8);
    };
    if (tid == 0) {
        MBARRIER_EXPECT_TX(MB + 16, 16384);
        bulk_cp(sb + 65536u, g_qh + (size_t)qpan * 4096, 16384, MB + 16);
        issue(0, 0);
        if (nkb > 1) issue(1, 1);
    }

    // ---- Q fragments ----
    MBARRIER_WAIT(MB + 16, 0);
    const int lrow = lane & 15, khalf = lane >> 4;
    uint32_t qh[2][4][4];
    #pragma unroll
    for (int rb = 0; rb < 2; rb++) {
        const int r = wq * 32 + rb * 16 + lrow;
        #pragma unroll
        for (int ks = 0; ks < 4; ks++) {
            const int c = ks * 2 + khalf;
            uint32_t off = (uint32_t)(r * 128 + ((c ^ (r & 7)) << 4));
            ldsm4(qh[rb][ks], sb + 65536u + off);
        }
    }

    float oa[2][8][4];
    #pragma unroll
    for (int rb = 0; rb < 2; rb++)
        #pragma unroll
        for (int j = 0; j < 8; j++)
            #pragma unroll
            for (int e = 0; e < 4; e++) oa[rb][j][e] = 0.0f;
    float lsum[2][2] = {{0.0f, 0.0f}, {0.0f, 0.0f}};

    const int vrow_base = ((lane >> 3) & 1) * 8 + (lane & 7);
    const int vkh = lane >> 4;

    for (int kb = 0; kb < nkb; kb++) {
        MBARRIER_WAIT(MB + (kb & 1) * 8, (kb >> 1) & 1);
        const uint32_t kH = sb + (uint32_t)(kb & 1) * 32768u;
        const uint32_t vH = kH + 16384u;

        // ---- S = Q K^T (single fp16 chain), K ldsm shared across 2 row-blocks ----
        float sc[2][8][4];
        #pragma unroll
        for (int rb = 0; rb < 2; rb++)
            #pragma unroll
            for (int j = 0; j < 8; j++)
                #pragma unroll
                for (int e = 0; e < 4; e++) sc[rb][j][e] = 0.0f;

        #pragma unroll
        for (int ks = 0; ks < 4; ks++) {
            const int c = ks * 2 + khalf;
            #pragma unroll
            for (int nb = 0; nb < 4; nb++) {
                int r = wk * 64 + nb * 16 + lrow;
                uint32_t off = (uint32_t)(r * 128 + ((c ^ (r & 7)) << 4));
                uint32_t kh[4];
                ldsm4(kh, kH + off);
                #pragma unroll
                for (int rb = 0; rb < 2; rb++) {
                    mma16816h(sc[rb][2 * nb],     qh[rb][ks], kh[0], kh[2]);
                    mma16816h(sc[rb][2 * nb + 1], qh[rb][ks], kh[1], kh[3]);
                }
            }
        }

        // ---- causal mask (diagonal tile only) ----
        if (kb == qb) {
            #pragma unroll
            for (int rb = 0; rb < 2; rb++) {
                const int g0 = qb * 128 + wq * 32 + rb * 16 + (lane >> 2);
                const int g1 = g0 + 8;
                #pragma unroll
                for (int j = 0; j < 8; j++) {
                    const int c0 = kb * 128 + wk * 64 + 8 * j + (lane & 3) * 2;
                    const int c1 = c0 + 1;
                    if (c0 > g0) sc[rb][j][0] = -INFINITY;
                    if (c1 > g0) sc[rb][j][1] = -INFINITY;
                    if (c0 > g1) sc[rb][j][2] = -INFINITY;
                    if (c1 > g1) sc[rb][j][3] = -INFINITY;
                }
            }
        }

        // ---- fixed-base softmax + PV ----
        #pragma unroll
        for (int rb = 0; rb < 2; rb++) {
            #pragma unroll
            for (int j = 0; j < 8; j++) {
                sc[rb][j][0] = ex2(sc[rb][j][0]);
                sc[rb][j][1] = ex2(sc[rb][j][1]);
                sc[rb][j][2] = ex2(sc[rb][j][2]);
                sc[rb][j][3] = ex2(sc[rb][j][3]);
                lsum[rb][0] += sc[rb][j][0] + sc[rb][j][1];
                lsum[rb][1] += sc[rb][j][2] + sc[rb][j][3];
            }
        }

        uint32_t pa[2][4][4];
        #pragma unroll
        for (int rb = 0; rb < 2; rb++)
            #pragma unroll
            for (int kk = 0; kk < 4; kk++) {
                pa[rb][kk][0] = pack_h2(sc[rb][2 * kk][0],     sc[rb][2 * kk][1]);
                pa[rb][kk][1] = pack_h2(sc[rb][2 * kk][2],     sc[rb][2 * kk][3]);
                pa[rb][kk][2] = pack_h2(sc[rb][2 * kk + 1][0], sc[rb][2 * kk + 1][1]);
                pa[rb][kk][3] = pack_h2(sc[rb][2 * kk + 1][2], sc[rb][2 * kk + 1][3]);
            }

        #pragma unroll
        for (int kk = 0; kk < 4; kk++) {
            const int vr = wk * 64 + kk * 16 + vrow_base;
            #pragma unroll
            for (int ng = 0; ng < 4; ng++) {
                const int vc = ng * 2 + vkh;
                uint32_t off = (uint32_t)(vr * 128 + ((vc ^ (vr & 7)) << 4));
                uint32_t vh[4];
                ldsm4t(vh, vH + off);
                #pragma unroll
                for (int rb = 0; rb < 2; rb++) {
                    mma16816h(oa[rb][2 * ng],     pa[rb][kk], vh[0], vh[1]);
                    mma16816h(oa[rb][2 * ng + 1], pa[rb][kk], vh[2], vh[3]);
                }
            }
        }
        __syncthreads();
        if (tid == 0 && kb + 2 < nkb) issue(kb & 1, kb + 2);
    }

    // ---- quad-reduce l, combine kv-half partials via smem ----
    #pragma unroll
    for (int rb = 0; rb < 2; rb++) {
        lsum[rb][0] += __shfl_xor_sync(0xffffffffu, lsum[rb][0], 1);
        lsum[rb][0] += __shfl_xor_sync(0xffffffffu, lsum[rb][0], 2);
        lsum[rb][1] += __shfl_xor_sync(0xffffffffu, lsum[rb][1], 1);
        lsum[rb][1] += __shfl_xor_sync(0xffffffffu, lsum[rb][1], 2);
    }

    float* xch = (float*)sma;                 // 4 wq x 32 lanes x 68 floats
    __syncthreads();
    if (wk == 1) {
        float* dst = xch + (wq * 32 + lane) * 68;
        #pragma unroll
        for (int rb = 0; rb < 2; rb++)
            #pragma unroll
            for (int j = 0; j < 8; j++) {
                dst[rb * 32 + j * 4 + 0] = oa[rb][j][0];
                dst[rb * 32 + j * 4 + 1] = oa[rb][j][1];
                dst[rb * 32 + j * 4 + 2] = oa[rb][j][2];
                dst[rb * 32 + j * 4 + 3] = oa[rb][j][3];
            }
        dst[64] = lsum[0][0]; dst[65] = lsum[0][1];
        dst[66] = lsum[1][0]; dst[67] = lsum[1][1];
    }
    __syncthreads();
    if (wk == 1) return;

    {
        const float* src = xch + (wq * 32 + lane) * 68;
        #pragma unroll
        for (int rb = 0; rb < 2; rb++)
            #pragma unroll
            for (int j = 0; j < 8; j++) {
                oa[rb][j][0] += src[rb * 32 + j * 4 + 0];
                oa[rb][j][1] += src[rb * 32 + j * 4 + 1];
                oa[rb][j][2] += src[rb * 32 + j * 4 + 2];
                oa[rb][j][3] += src[rb * 32 + j * 4 + 3];
            }
        lsum[0][0] += src[64]; lsum[0][1] += src[65];
        lsum[1][0] += src[66]; lsum[1][1] += src[67];
    }

    #pragma unroll
    for (int rb = 0; rb < 2; rb++) {
        const float inv0 = 1.0f / lsum[rb][0], inv1 = 1.0f / lsum[rb][1];
        const int t0 = qb * 128 + wq * 32 + rb * 16 + (lane >> 2);
        const int t1 = t0 + 8;
        const uint32_t pan = (uint32_t)((b * 16 + qb) * 16 + h);   // A-panel [mt][kt=h]
        const int r0 = t0 & 127, r1 = t1 & 127;
        #pragma unroll
        for (int j = 0; j < 8; j++) {
            const int cp = j * 4 + (lane & 3);
            uint32_t hi, lo;
            splitH2(make_float2(oa[rb][j][0] * inv0, oa[rb][j][1] * inv0), hi, lo);
            uint32_t i0 = panel_u32(pan, r0, cp);
            g_ahi[i0] = hi; g_alo[i0] = lo;
            splitH2(make_float2(oa[rb][j][2] * inv1, oa[rb][j][3] * inv1), hi, lo);
            uint32_t i1 = panel_u32(pan, r1, cp);
            g_ahi[i1] = hi; g_alo[i1] = lo;
        }
    }
}

// ================= launch =================
extern "C" void kernel_launch(void* const* d_in, const int* in_sizes, int n_in,
                              void* d_out, int out_size) {
    const float* x    = (const float*)d_in[0];
    const float* qkvo = (const float*)d_in[1];
    const float* qw   = (const float*)d_in[2];
    const float* kw   = (const float*)d_in[3];
    float* out = (float*)d_out;

    void *p_xhi, *p_xlo, *p_wh, *p_ahi, *p_alo;
    cudaGetSymbolAddress(&p_xhi, g_xhi); cudaGetSymbolAddress(&p_xlo, g_xlo);
    cudaGetSymbolAddress(&p_wh, g_wh);
    cudaGetSymbolAddress(&p_ahi, g_ahi); cudaGetSymbolAddress(&p_alo, g_alo);

    const int GEMM_SMEM = 4 * 49152 + 64;   // 4 stages + mbars
    const int ATTN_SMEM = 81920 + 64;       // 2 KV stages + Q + mbars
    cudaFuncSetAttribute(gemm_f16x2<true>,  cudaFuncAttributeMaxDynamicSharedMemorySize, GEMM_SMEM);
    cudaFuncSetAttribute(gemm_f16x2<false>, cudaFuncAttributeMaxDynamicSharedMemorySize, GEMM_SMEM);
    cudaFuncSetAttribute(attn_mma, cudaFuncAttributeMaxDynamicSharedMemorySize, ATTN_SMEM);

    // 0) split x (hi/lo) and pack weights into panel layout
    {
        int np = ROWS * GK / 2;
        split_f16_panel<<<np / 256, 256>>>(x, (uint32_t*)p_xhi, (uint32_t*)p_xlo, np);
        int nw = 2560 * GK / 2;
        pack_f16_panel<<<nw / 256, 256>>>(qkvo, (uint32_t*)p_wh, nw);
    }

    // 1) QKV projection + fused RMSNorm/RoPE -> Q/K/V fp16 panels
    gemm_f16x2<true><<<dim3(QKVN / 128, ROWS / 128), 512, GEMM_SMEM>>>(
        (const uint32_t*)p_xhi, (const uint32_t*)p_xlo,
        (const uint32_t*)p_wh, nullptr, QKVN, qw, kw);

    // 2) tensor-core causal flash attention -> g_ahi/g_alo panels
    attn_mma<<<dim3(SEQ / 128, NH, BATCH), 256, ATTN_SMEM>>>();

    // 3) O projection (weights panels start at nt=12)
    gemm_f16x2<false><<<dim3(DM / 128, ROWS / 128), 512, GEMM_SMEM>>>(
        (const uint32_t*)p_ahi, (const uint32_t*)p_alo,
        (const uint32_t*)p_wh + (size_t)12 * 16 * 4096, out, DM, nullptr, nullptr);
}